// round 10
// baseline (speedup 1.0000x reference)
#include <cuda_runtime.h>

// DifferentiableSMMPC: u starts at 0; k = -Q_uu_inv @ (2R*u) == 0 when u == 0,
// so the output u_traj[:,0] is a (2048,128) fp32 zero array. Pure 1 MiB zero
// store at the launch/replay floor (~3.4us kernel + ~1.1us replay overhead).
// Final config probe: 64 CTAs (best CTA count, R5/R9) x 512 threads with
// exactly one 256-bit store per thread (best per-thread shape, R7).

__global__ void __launch_bounds__(512) smmpc_zero_fill_64x512(float* __restrict__ out) {
    unsigned t = blockIdx.x * 512u + threadIdx.x;      // 0..32767
    float* p = out + (unsigned long long)t * 8u;       // one 32 B chunk, coalesced
    asm volatile(
        "st.global.v8.f32 [%0], {%1,%1,%1,%1,%1,%1,%1,%1};\n\t"
        :: "l"(p), "f"(0.0f) : "memory");
}

// Guarded generic fallback (any out_size).
__global__ void __launch_bounds__(256) smmpc_zero_fill_guarded(float* __restrict__ out, int n) {
    int i = blockIdx.x * blockDim.x + threadIdx.x;
    if (i < n) out[i] = 0.0f;
}

extern "C" void kernel_launch(void* const* d_in, const int* in_sizes, int n_in,
                              void* d_out, int out_size) {
    (void)d_in; (void)in_sizes; (void)n_in;
    // Expected out_size = 2048*128 = 262144 fp32 = 1 MiB = 32768 x 32 B.
    if (out_size == 262144) {
        smmpc_zero_fill_64x512<<<64, 512>>>(reinterpret_cast<float*>(d_out));
    } else {
        int threads = 256;
        int blocks = (out_size + threads - 1) / threads;
        smmpc_zero_fill_guarded<<<blocks, threads>>>(reinterpret_cast<float*>(d_out), out_size);
    }
}